// round 1
// baseline (speedup 1.0000x reference)
#include <cuda_runtime.h>
#include <stdint.h>

// Problem constants (StationSelectionAggregator):
//   schedule: [B, WIN, N_ST]  one-hot float32
//   csi:      [B, N_ST, N_SUB, WIN] float32
//   out:      [B, WIN, N_SUB] float32
//   out[b,w,s] = sum_t csi[b,t,s,w] * schedule[b,w,t]  == csi[b, t(b,w), s, w]
//   since schedule is exactly one-hot (values exactly 0.0f / 1.0f).
#define B_    32
#define NST   8
#define NSUB  256
#define WIN   2048

__global__ __launch_bounds__(256)
void station_select_kernel(const float* __restrict__ sched,
                           const float* __restrict__ csi,
                           float* __restrict__ out) {
    // blockIdx.x : w tile   (WIN/32  = 64)
    // blockIdx.y : s tile   (NSUB/32 = 8)
    // blockIdx.z : batch    (32)
    __shared__ float tile[32][33];   // [s_local][w_local], +1 pad vs bank conflicts
    __shared__ int   tw[32];         // selected station per w in this tile

    const int b  = blockIdx.z;
    const int w0 = blockIdx.x * 32;
    const int s0 = blockIdx.y * 32;
    const int tx = threadIdx.x;      // 0..31
    const int ty = threadIdx.y;      // 0..7
    const int tid = ty * 32 + tx;

    // --- recover station index per w from the one-hot row (exact: values are 0.0/1.0) ---
    if (tid < 32) {
        const float4* sp = reinterpret_cast<const float4*>(
            sched + ((size_t)b * WIN + (size_t)(w0 + tid)) * NST);
        float4 a = sp[0];
        float4 c = sp[1];
        float tf = a.y + 2.f * a.z + 3.f * a.w +
                   4.f * c.x + 5.f * c.y + 6.f * c.z + 7.f * c.w;
        tw[tid] = (int)(tf + 0.5f);
    }
    __syncthreads();

    // --- gather reads: coalesced along w (tx), scattered across the 8 t-planes ---
    const int t = tw[tx];
    const size_t base = ((size_t)(b * NST + t) * NSUB) * WIN + (size_t)(w0 + tx);
#pragma unroll
    for (int r = 0; r < 4; r++) {
        const int sl = ty + r * 8;               // s_local 0..31
        tile[sl][tx] = csi[base + (size_t)(s0 + sl) * WIN];
    }
    __syncthreads();

    // --- transposed writes: coalesced along s (tx) ---
#pragma unroll
    for (int r = 0; r < 4; r++) {
        const int wl = ty + r * 8;               // w_local 0..31
        out[((size_t)b * WIN + (size_t)(w0 + wl)) * NSUB + (size_t)(s0 + tx)]
            = tile[tx][wl];
    }
}

extern "C" void kernel_launch(void* const* d_in, const int* in_sizes, int n_in,
                              void* d_out, int out_size) {
    // Map inputs by element count (defensive against ordering):
    //   schedule: 32*2048*8     = 524288
    //   csi:      32*8*256*2048 = 134217728
    const float* sched = (const float*)d_in[0];
    const float* csi   = (const float*)d_in[1];
    if (n_in >= 2 && in_sizes[0] != 524288) {
        sched = (const float*)d_in[1];
        csi   = (const float*)d_in[0];
    }
    float* out = (float*)d_out;

    dim3 block(32, 8, 1);
    dim3 grid(WIN / 32, NSUB / 32, B_);
    station_select_kernel<<<grid, block>>>(sched, csi, out);
}